// round 3
// baseline (speedup 1.0000x reference)
#include <cuda_runtime.h>
#include <cuda_fp16.h>

#define H        64
#define NPIX     65536
#define LBATCH   8
#define NLC      24
#define NSPLIT   64                      // K-splits (warps) per (l,c)
#define PIX_PER_WARP (NPIX / NSPLIT)     // 1024
#define NCHUNK   (PIX_PER_WARP / 32)     // 32 chunks of 32 pixels

// scratch: per-warp partial 64x64 tiles, [NLC][NSPLIT][H*H]
__device__ float g_part[NLC * NSPLIT * H * H];
__device__ float g_totals[LBATCH];

__device__ __forceinline__ float rq(float d) {
    // 1 / (1 + d*d)
    float t = fmaf(d, d, 1.0f);
    float r; asm("rcp.approx.ftz.f32 %0, %1;" : "=f"(r) : "f"(t));
    return r;
}
__device__ __forceinline__ unsigned pk(float lo, float hi) {
    // pack two f32 -> f16x2, lo in lower half
    unsigned r; asm("cvt.rn.f16x2.f32 %0, %2, %1;" : "=r"(r) : "f"(lo), "f"(hi));
    return r;
}
__device__ __forceinline__ float lg2a(float x) {
    float r; asm("lg2.approx.f32 %0, %1;" : "=f"(r) : "f"(x));
    return r;
}
__device__ __forceinline__ float sqrta(float x) {
    float r; asm("sqrt.approx.f32 %0, %1;" : "=f"(r) : "f"(x));
    return r;
}
__device__ __forceinline__ void mma16816(float* c, const unsigned* a, unsigned b0, unsigned b1) {
    asm volatile(
        "mma.sync.aligned.m16n8k16.row.col.f32.f16.f16.f32 "
        "{%0,%1,%2,%3}, {%4,%5,%6,%7}, {%8,%9}, {%0,%1,%2,%3};"
        : "+f"(c[0]), "+f"(c[1]), "+f"(c[2]), "+f"(c[3])
        : "r"(a[0]), "r"(a[1]), "r"(a[2]), "r"(a[3]), "r"(b0), "r"(b1));
}

// grid: (NSPLIT, NLC), block: 32 threads (one warp)
__global__ __launch_bounds__(32) void hist_main(const float* __restrict__ x) {
    const int lane = threadIdx.x;
    const int lc = blockIdx.y;
    const int l = lc / 3, c = lc % 3;
    const float* __restrict__ xl = x + (size_t)l * 3 * NPIX;
    const int pixbase = blockIdx.x * PIX_PER_WARP;

    float acc[4][8][4];
#pragma unroll
    for (int m = 0; m < 4; m++)
#pragma unroll
        for (int j = 0; j < 8; j++)
#pragma unroll
            for (int k = 0; k < 4; k++) acc[m][j][k] = 0.0f;

    // bin centers in scaled coords: off(i) = (-3 + i*6/63) / sigma, sigma = 0.02
    float rowoff[8];
#pragma unroll
    for (int i = 0; i < 8; i++)
        rowoff[i] = (-3.0f + (float)((lane >> 2) + 8 * i) * (6.0f / 63.0f)) * 50.0f;

    const float SC = 34.65735903f;  // ln(2) / sigma  (lg2 -> ln, then /sigma)
    const int kc = (lane & 3) * 2;

#pragma unroll 1
    for (int ch = 0; ch < NCHUNK; ch++) {
        const int p = pixbase + ch * 32 + lane;
        float i0 = fminf(fmaxf(xl[p], 0.0f), 1.0f);
        float i1 = fminf(fmaxf(xl[p + NPIX], 0.0f), 1.0f);
        float i2 = fminf(fmaxf(xl[p + 2 * NPIX], 0.0f), 1.0f);
        float w = sqrta(fmaf(i0, i0, fmaf(i1, i1, fmaf(i2, i2, 1e-6f))));
        float g0 = lg2a(i0 + 1e-6f);
        float g1 = lg2a(i1 + 1e-6f);
        float g2 = lg2a(i2 + 1e-6f);
        // per-channel log-chromaticity, scaled by 1/sigma
        float au, av;
        if (c == 0)      { au = (g0 - g1) * SC; av = (g0 - g2) * SC; }
        else if (c == 1) { au = (g1 - g0) * SC; av = (g1 - g2) * SC; }
        else             { au = (g2 - g0) * SC; av = (g2 - g1) * SC; }

#pragma unroll
        for (int s = 0; s < 2; s++) {
            const int sb = s * 16 + kc;
            float au0 = __shfl_sync(0xffffffffu, au, sb);
            float au1 = __shfl_sync(0xffffffffu, au, sb + 1);
            float au2 = __shfl_sync(0xffffffffu, au, sb + 8);
            float au3 = __shfl_sync(0xffffffffu, au, sb + 9);
            float av0 = __shfl_sync(0xffffffffu, av, sb);
            float av1 = __shfl_sync(0xffffffffu, av, sb + 1);
            float av2 = __shfl_sync(0xffffffffu, av, sb + 8);
            float av3 = __shfl_sync(0xffffffffu, av, sb + 9);
            float w0 = __shfl_sync(0xffffffffu, w, sb);
            float w1 = __shfl_sync(0xffffffffu, w, sb + 1);
            float w2 = __shfl_sync(0xffffffffu, w, sb + 8);
            float w3 = __shfl_sync(0xffffffffu, w, sb + 9);

            // A fragments: A[u][k] = w_k * Ku  (4 M-tiles of 16 rows)
            unsigned a[4][4];
#pragma unroll
            for (int m = 0; m < 4; m++) {
                const float o0 = rowoff[2 * m];      // row r = lane/4 + 16m
                const float o1 = rowoff[2 * m + 1];  // row r + 8
                a[m][0] = pk(w0 * rq(au0 - o0), w1 * rq(au1 - o0));
                a[m][1] = pk(w0 * rq(au0 - o1), w1 * rq(au1 - o1));
                a[m][2] = pk(w2 * rq(au2 - o0), w3 * rq(au3 - o0));
                a[m][3] = pk(w2 * rq(au2 - o1), w3 * rq(au3 - o1));
            }
            // B fragments per N-tile j: B[k][v] = Kv, col v = lane/4 + 8j
#pragma unroll
            for (int j = 0; j < 8; j++) {
                const float o = rowoff[j];
                unsigned b0 = pk(rq(av0 - o), rq(av1 - o));
                unsigned b1 = pk(rq(av2 - o), rq(av3 - o));
#pragma unroll
                for (int m = 0; m < 4; m++) mma16816(acc[m][j], a[m], b0, b1);
            }
        }
    }

    // store partial tile (non-atomic, private slot)
    float* dst = g_part + ((size_t)lc * NSPLIT + blockIdx.x) * (H * H);
    const int r = lane >> 2;
    const int q = (lane & 3) * 2;
#pragma unroll
    for (int m = 0; m < 4; m++)
#pragma unroll
        for (int j = 0; j < 8; j++) {
            const int row0 = m * 16 + r;
            const int col = j * 8 + q;
            *(float2*)(dst + row0 * H + col)       = make_float2(acc[m][j][0], acc[m][j][1]);
            *(float2*)(dst + (row0 + 8) * H + col) = make_float2(acc[m][j][2], acc[m][j][3]);
        }
}

__global__ void zero_totals() {
    if (threadIdx.x < LBATCH) g_totals[threadIdx.x] = 0.0f;
}

// grid: (16, NLC), block 256 — sum 64 partials per element; accumulate per-l totals
__global__ void hist_reduce(float* __restrict__ out) {
    const int lc = blockIdx.y;
    const int e = blockIdx.x * 256 + threadIdx.x;  // 0..4095
    const float* __restrict__ src = g_part + (size_t)lc * NSPLIT * (H * H) + e;
    float s = 0.0f;
#pragma unroll 8
    for (int p = 0; p < NSPLIT; p++) s += src[(size_t)p * (H * H)];
    out[lc * (H * H) + e] = s;

    __shared__ float red[256];
    red[threadIdx.x] = s;
    __syncthreads();
#pragma unroll
    for (int st = 128; st > 0; st >>= 1) {
        if (threadIdx.x < st) red[threadIdx.x] += red[threadIdx.x + st];
        __syncthreads();
    }
    if (threadIdx.x == 0) atomicAdd(&g_totals[lc / 3], red[0]);
}

__global__ void hist_norm(float* __restrict__ out) {
    const int idx = blockIdx.x * 256 + threadIdx.x;
    if (idx < NLC * H * H) {
        const int l = idx / (3 * H * H);
        out[idx] = out[idx] / (g_totals[l] + 1e-6f);
    }
}

extern "C" void kernel_launch(void* const* d_in, const int* in_sizes, int n_in,
                              void* d_out, int out_size) {
    const float* x = (const float*)d_in[0];
    float* out = (float*)d_out;
    (void)in_sizes; (void)n_in; (void)out_size;

    zero_totals<<<1, 32>>>();
    hist_main<<<dim3(NSPLIT, NLC), 32>>>(x);
    hist_reduce<<<dim3(16, NLC), 256>>>(out);
    hist_norm<<<(NLC * H * H + 255) / 256, 256>>>(out);
}

// round 4
// speedup vs baseline: 1.1336x; 1.1336x over previous
#include <cuda_runtime.h>
#include <cuda_fp16.h>

#define H        64
#define NPIX     65536
#define LBATCH   8
#define NSPLIT   74                      // K-splits per l; 8*74 = 592 = 148 SM * 4 CTAs
#define NCTA     (LBATCH * NSPLIT)
#define NCHUNKS  2048                    // 32-pixel chunks per image

// scratch: per-CTA 3 GEMM tiles: [l][split][gemm][64*64]
__device__ float g_part[(size_t)NCTA * 3 * H * H];
// per-reduce-block partial totals: [l][c][16 blocks]
__device__ float g_bsum[LBATCH * 3 * 16];

__device__ __forceinline__ float rq(float d) {          // 1/(1+d*d)
    float t = fmaf(d, d, 1.0f);
    float r; asm("rcp.approx.ftz.f32 %0, %1;" : "=f"(r) : "f"(t));
    return r;
}
__device__ __forceinline__ unsigned pk(float lo, float hi) {  // f32x2 -> f16x2
    unsigned r; asm("cvt.rn.f16x2.f32 %0, %2, %1;" : "=r"(r) : "f"(lo), "f"(hi));
    return r;
}
__device__ __forceinline__ unsigned hm2(unsigned a, unsigned b) {
    unsigned r; asm("mul.rn.f16x2 %0, %1, %2;" : "=r"(r) : "r"(a), "r"(b));
    return r;
}
__device__ __forceinline__ float lg2a(float x) {
    float r; asm("lg2.approx.f32 %0, %1;" : "=f"(r) : "f"(x));
    return r;
}
__device__ __forceinline__ float sqrta(float x) {
    float r; asm("sqrt.approx.f32 %0, %1;" : "=f"(r) : "f"(x));
    return r;
}
__device__ __forceinline__ void mma16816(float* c, const unsigned* a, unsigned b0, unsigned b1) {
    asm volatile(
        "mma.sync.aligned.m16n8k16.row.col.f32.f16.f16.f32 "
        "{%0,%1,%2,%3}, {%4,%5,%6,%7}, {%8,%9}, {%0,%1,%2,%3};"
        : "+f"(c[0]), "+f"(c[1]), "+f"(c[2]), "+f"(c[3])
        : "r"(a[0]), "r"(a[1]), "r"(a[2]), "r"(a[3]), "r"(b0), "r"(b1));
}

// grid: NCTA blocks of 96 threads (3 warps). Warp w:
//   - loads channel w, computes log diff d_w (w0:g0-g1, w1:g0-g2, w2:g1-g2)
//   - produces vector w's fragment image (sqrt(w)-folded f16 K values)
//   - consumes GEMM w: w0: K01(A)*K02(B); w1: K01(A)*K12(B); w2: K02(A)*K12(B)
__global__ __launch_bounds__(96, 4) void hist_main(const float* __restrict__ x) {
    __shared__ uint4 img[3 * 2 * 4 * 32];   // [vec][step][mtile][lane], 12 KB
    __shared__ float sh_i[3][32];
    __shared__ float sh_d[3][32];
    __shared__ unsigned sh_swp[16];          // packed f16x2 sqrt(w) per pixel pair

    const int tid = threadIdx.x;
    const int w = tid >> 5;
    const int L = tid & 31;
    const int bx = blockIdx.x;
    const int l = bx / NSPLIT, split = bx % NSPLIT;
    const int cbeg = (split * NCHUNKS) / NSPLIT;
    const int cend = ((split + 1) * NCHUNKS) / NSPLIT;
    const float* __restrict__ xw = x + ((size_t)l * 3 + w) * NPIX;

    float acc[4][8][4];
#pragma unroll
    for (int m = 0; m < 4; m++)
#pragma unroll
        for (int j = 0; j < 8; j++)
#pragma unroll
            for (int k = 0; k < 4; k++) acc[m][j][k] = 0.0f;

    float rowoff[8];
#pragma unroll
    for (int i = 0; i < 8; i++)
        rowoff[i] = (-3.0f + (float)((L >> 2) + 8 * i) * (6.0f / 63.0f)) * 50.0f;

    const int cha = w >> 1;                  // log channel pair per warp
    const int chb = (w == 0) ? 1 : 2;
    const int aimg = w >> 1;                 // A-operand image index per GEMM
    const int bimg = (w == 0) ? 1 : 2;       // B-operand image index
    const float SC = 34.65735903f;           // ln(2)/sigma (lg2 -> ln, /0.02)
    const int q = L & 3;

#pragma unroll 1
    for (int ch = cbeg; ch < cend; ch++) {
        // phase 1: load own channel, clip, publish
        float iv = fminf(fmaxf(xw[ch * 32 + L], 0.0f), 1.0f);
        sh_i[w][L] = iv;
        __syncthreads();

        // phase 2: per-pixel prep (each warp computes its own d; warp0 packs sqrt(w))
        {
            float i0 = sh_i[0][L], i1 = sh_i[1][L], i2 = sh_i[2][L];
            float ga = lg2a(sh_i[cha][L] + 1e-6f);
            float gb = lg2a(sh_i[chb][L] + 1e-6f);
            sh_d[w][L] = (ga - gb) * SC;
            if (w == 0) {
                float s = fmaf(i0, i0, fmaf(i1, i1, fmaf(i2, i2, 1e-6f)));
                float sw = sqrta(sqrta(s));   // w^(1/2) where w = sqrt(sum)
                float lo = __shfl_sync(0xffffffffu, sw, (L & 15) * 2);
                float hi = __shfl_sync(0xffffffffu, sw, (L & 15) * 2 + 1);
                if (L < 16) sh_swp[L] = pk(lo, hi);
            }
        }
        __syncthreads();

        // phase 3: produce own vector's fragment image for both 16-px steps
#pragma unroll
        for (int st = 0; st < 2; st++) {
            float2 dp0 = *(const float2*)&sh_d[w][(st * 8 + q) * 2];
            float2 dp1 = *(const float2*)&sh_d[w][(st * 8 + q + 4) * 2];
            unsigned s0 = sh_swp[st * 8 + q];
            unsigned s1 = sh_swp[st * 8 + q + 4];
#pragma unroll
            for (int m = 0; m < 4; m++) {
                const float o0 = rowoff[2 * m], o1 = rowoff[2 * m + 1];
                uint4 v;
                v.x = hm2(pk(rq(dp0.x - o0), rq(dp0.y - o0)), s0);
                v.y = hm2(pk(rq(dp0.x - o1), rq(dp0.y - o1)), s0);
                v.z = hm2(pk(rq(dp1.x - o0), rq(dp1.y - o0)), s1);
                v.w = hm2(pk(rq(dp1.x - o1), rq(dp1.y - o1)), s1);
                img[((w * 2 + st) * 4 + m) * 32 + L] = v;
            }
        }
        __syncthreads();

        // phase 4: consume — 64 MMAs per warp (2 steps x 4 mtiles x 8 jtiles)
#pragma unroll
        for (int st = 0; st < 2; st++) {
            uint4 A0 = img[((aimg * 2 + st) * 4 + 0) * 32 + L];
            uint4 A1 = img[((aimg * 2 + st) * 4 + 1) * 32 + L];
            uint4 A2 = img[((aimg * 2 + st) * 4 + 2) * 32 + L];
            uint4 A3 = img[((aimg * 2 + st) * 4 + 3) * 32 + L];
#pragma unroll
            for (int mp = 0; mp < 4; mp++) {
                uint4 W = img[((bimg * 2 + st) * 4 + mp) * 32 + L];
                // jtile 2*mp:   b0 = W.x, b1 = W.z
                // jtile 2*mp+1: b0 = W.y, b1 = W.w
                mma16816(acc[0][2 * mp], (const unsigned*)&A0, W.x, W.z);
                mma16816(acc[1][2 * mp], (const unsigned*)&A1, W.x, W.z);
                mma16816(acc[2][2 * mp], (const unsigned*)&A2, W.x, W.z);
                mma16816(acc[3][2 * mp], (const unsigned*)&A3, W.x, W.z);
                mma16816(acc[0][2 * mp + 1], (const unsigned*)&A0, W.y, W.w);
                mma16816(acc[1][2 * mp + 1], (const unsigned*)&A1, W.y, W.w);
                mma16816(acc[2][2 * mp + 1], (const unsigned*)&A2, W.y, W.w);
                mma16816(acc[3][2 * mp + 1], (const unsigned*)&A3, W.y, W.w);
            }
        }
    }

    // store this warp's GEMM tile (non-atomic, private slot)
    float* dst = g_part + ((size_t)bx * 3 + w) * (H * H);
    const int r = L >> 2;
    const int qq = (L & 3) * 2;
#pragma unroll
    for (int m = 0; m < 4; m++)
#pragma unroll
        for (int j = 0; j < 8; j++) {
            const int row0 = m * 16 + r;
            const int col = j * 8 + qq;
            *(float2*)(dst + row0 * H + col)       = make_float2(acc[m][j][0], acc[m][j][1]);
            *(float2*)(dst + (row0 + 8) * H + col) = make_float2(acc[m][j][2], acc[m][j][3]);
        }
}

// grid (16, 24), 256 threads. Sums 74 splits with the channel reversal mapping,
// writes out and a per-block partial total (no atomics, no zeroing needed).
__global__ void hist_reduce(float* __restrict__ out) {
    const int lc = blockIdx.y;
    const int c = lc % 3, lidx = lc / 3;
    const int e = blockIdx.x * 256 + threadIdx.x;  // 0..4095
    const int u = e >> 6, v = e & 63;
    int se;
    if (c == 0)      se = e;                        // identity
    else if (c == 1) se = ((63 - u) << 6) | v;      // row reversal
    else             se = 4095 - e;                 // row+col reversal
    const float* __restrict__ src =
        g_part + ((size_t)(lidx * NSPLIT) * 3 + c) * (H * H) + se;
    float s = 0.0f;
#pragma unroll 2
    for (int sp = 0; sp < NSPLIT; sp++) s += src[(size_t)sp * 3 * (H * H)];
    out[lc * (H * H) + e] = s;

    __shared__ float red[256];
    red[threadIdx.x] = s;
    __syncthreads();
#pragma unroll
    for (int st = 128; st > 0; st >>= 1) {
        if (threadIdx.x < st) red[threadIdx.x] += red[threadIdx.x + st];
        __syncthreads();
    }
    if (threadIdx.x == 0)
        g_bsum[lc * 16 + blockIdx.x] = red[0];
}

// grid 384, 256 threads. Each block covers 256 contiguous outputs (same l).
__global__ void hist_norm(float* __restrict__ out) {
    __shared__ float red[48];
    const int l = blockIdx.x / 48;                  // 12288 per l / 256 = 48 blocks
    if (threadIdx.x < 48) red[threadIdx.x] = g_bsum[l * 48 + threadIdx.x];
    __syncthreads();
    float tot = 1e-6f;
#pragma unroll
    for (int k = 0; k < 48; k++) tot += red[k];
    const int idx = blockIdx.x * 256 + threadIdx.x;
    out[idx] = out[idx] / tot;
}

extern "C" void kernel_launch(void* const* d_in, const int* in_sizes, int n_in,
                              void* d_out, int out_size) {
    const float* x = (const float*)d_in[0];
    float* out = (float*)d_out;
    (void)in_sizes; (void)n_in; (void)out_size;

    hist_main<<<NCTA, 96>>>(x);
    hist_reduce<<<dim3(16, 24), 256>>>(out);
    hist_norm<<<384, 256>>>(out);
}

// round 5
// speedup vs baseline: 1.2179x; 1.0743x over previous
#include <cuda_runtime.h>
#include <cuda_fp16.h>

#define H        64
#define NPIX     65536
#define LBATCH   8
#define NSPLIT   55                      // 8*55 = 440 CTAs = 148 SMs * 3 CTAs (1 wave)
#define NCTA     (LBATCH * NSPLIT)
#define NCHUNKS  1024                    // 64-pixel chunks per image

// scratch: per-CTA 3 GEMM tiles: [cta][gemm][64*64]
__device__ float g_part[(size_t)NCTA * 3 * H * H];
// per-reduce-block partial totals: [l][c][16 blocks]
__device__ float g_bsum[LBATCH * 3 * 16];

__device__ __forceinline__ unsigned pk(float lo, float hi) {  // f32x2 -> f16x2
    unsigned r; asm("cvt.rn.f16x2.f32 %0, %2, %1;" : "=r"(r) : "f"(lo), "f"(hi));
    return r;
}
__device__ __forceinline__ unsigned hm2(unsigned a, unsigned b) {
    unsigned r; asm("mul.rn.f16x2 %0, %1, %2;" : "=r"(r) : "r"(a), "r"(b));
    return r;
}
__device__ __forceinline__ float lg2a(float x) {
    float r; asm("lg2.approx.f32 %0, %1;" : "=f"(r) : "f"(x));
    return r;
}
__device__ __forceinline__ float sqrta(float x) {
    float r; asm("sqrt.approx.f32 %0, %1;" : "=f"(r) : "f"(x));
    return r;
}
// two kernel values (pixels u0,u1 at same bin), sqrt-weight folded:
//   sw2 * 1/(1 + u^2), computed in f16x2 (1 MUFU for 2 values)
__device__ __forceinline__ unsigned kv(float u0, float u1, unsigned sw2) {
    unsigned u = pk(u0, u1);
    unsigned t;
    asm("fma.rn.f16x2 %0, %1, %1, %2;" : "=r"(t) : "r"(u), "r"(0x3C003C00u));
    __half2 th = *(__half2*)&t;
    __half2 rh = h2rcp(th);
    return hm2(*(unsigned*)&rh, sw2);
}
__device__ __forceinline__ void mma16816(float* c, const unsigned* a, unsigned b0, unsigned b1) {
    asm volatile(
        "mma.sync.aligned.m16n8k16.row.col.f32.f16.f16.f32 "
        "{%0,%1,%2,%3}, {%4,%5,%6,%7}, {%8,%9}, {%0,%1,%2,%3};"
        : "+f"(c[0]), "+f"(c[1]), "+f"(c[2]), "+f"(c[3])
        : "r"(a[0]), "r"(a[1]), "r"(a[2]), "r"(a[3]), "r"(b0), "r"(b1));
}

// 6 warps per CTA. Warp w: g = w%3, h = w/3.
//  P1: loads channel g, pixel-half h
//  P2: computes d[g] for half h (g==0 warps also pack sqrt-weights)
//  P3: produces vec g's fragment images for K-steps {2h, 2h+1}
//  P4: consumes GEMM g (A=img[g>>1], B=img[g?2:1]), N-columns [32h, 32h+32)
__global__ __launch_bounds__(192, 3) void hist_main(const float* __restrict__ x) {
    __shared__ uint4 img[3 * 4 * 4 * 32];   // [vec][st][mtile][lane], 24 KB
    __shared__ float sh_i[3][64];
    __shared__ float sh_d[3][64];
    __shared__ unsigned sh_swp[32];          // f16x2 sqrt(w) per pixel pair

    const int tid = threadIdx.x;
    const int w = tid >> 5;
    const int L = tid & 31;
    const int g = w % 3, h = w / 3;
    const int bx = blockIdx.x;
    const int l = bx / NSPLIT, split = bx % NSPLIT;
    const int cbeg = (split * NCHUNKS) / NSPLIT;
    const int cend = ((split + 1) * NCHUNKS) / NSPLIT;
    const float* __restrict__ xw = x + ((size_t)l * 3 + g) * NPIX;

    float acc[4][4][4];
#pragma unroll
    for (int m = 0; m < 4; m++)
#pragma unroll
        for (int j = 0; j < 4; j++)
#pragma unroll
            for (int k = 0; k < 4; k++) acc[m][j][k] = 0.0f;

    float rowoff[8];
#pragma unroll
    for (int i = 0; i < 8; i++)
        rowoff[i] = (-3.0f + (float)((L >> 2) + 8 * i) * (6.0f / 63.0f)) * 50.0f;

    const int cha = g >> 1;                  // log channel pair: g0:(0,1) g1:(0,2) g2:(1,2)
    const int chb = (g == 0) ? 1 : 2;
    const int aimg = g >> 1;                 // A-operand image per GEMM
    const int bimg = (g == 0) ? 1 : 2;       // B-operand image per GEMM
    const float SC = 34.65735903f;           // ln(2)/sigma
    const int q = L & 3;
    const int p = 32 * h + L;                // this warp's pixel slot in chunk

#pragma unroll 1
    for (int ch = cbeg; ch < cend; ch++) {
        // P1: load own (channel, half), clip, publish
        float iv = fminf(fmaxf(xw[ch * 64 + p], 0.0f), 1.0f);
        sh_i[g][p] = iv;
        __syncthreads();

        // P2: per-pixel log-chromaticity; vec0 warps also pack sqrt-weights
        {
            float ga = lg2a(sh_i[cha][p] + 1e-6f);
            float gb = lg2a(sh_i[chb][p] + 1e-6f);
            sh_d[g][p] = (ga - gb) * SC;
            if (g == 0) {
                float i0 = sh_i[0][p], i1 = sh_i[1][p], i2 = sh_i[2][p];
                float s = fmaf(i0, i0, fmaf(i1, i1, fmaf(i2, i2, 1e-6f)));
                float sw = sqrta(sqrta(s));   // (sum)^(1/4) = sqrt(Iy)
                float lo = __shfl_sync(0xffffffffu, sw, (L & 15) * 2);
                float hi = __shfl_sync(0xffffffffu, sw, (L & 15) * 2 + 1);
                if (L < 16) sh_swp[16 * h + L] = pk(lo, hi);
            }
        }
        __syncthreads();

        // P3: produce vec g's fragment image for K-steps 2h, 2h+1
#pragma unroll
        for (int si = 0; si < 2; si++) {
            const int st = 2 * h + si;
            float2 dp0 = *(const float2*)&sh_d[g][st * 16 + 2 * q];
            float2 dp1 = *(const float2*)&sh_d[g][st * 16 + 2 * (q + 4)];
            unsigned s0 = sh_swp[st * 8 + q];
            unsigned s1 = sh_swp[st * 8 + q + 4];
#pragma unroll
            for (int m = 0; m < 4; m++) {
                const float o0 = rowoff[2 * m], o1 = rowoff[2 * m + 1];
                uint4 v;
                v.x = kv(dp0.x - o0, dp0.y - o0, s0);
                v.y = kv(dp0.x - o1, dp0.y - o1, s0);
                v.z = kv(dp1.x - o0, dp1.y - o0, s1);
                v.w = kv(dp1.x - o1, dp1.y - o1, s1);
                img[((g * 4 + st) * 4 + m) * 32 + L] = v;
            }
        }
        __syncthreads();

        // P4: consume — GEMM g, N-half h: 4 K-steps x 16 MMAs
#pragma unroll
        for (int st = 0; st < 4; st++) {
            uint4 A0 = img[((aimg * 4 + st) * 4 + 0) * 32 + L];
            uint4 A1 = img[((aimg * 4 + st) * 4 + 1) * 32 + L];
            uint4 A2 = img[((aimg * 4 + st) * 4 + 2) * 32 + L];
            uint4 A3 = img[((aimg * 4 + st) * 4 + 3) * 32 + L];
            uint4 W0 = img[((bimg * 4 + st) * 4 + 2 * h) * 32 + L];
            uint4 W1 = img[((bimg * 4 + st) * 4 + 2 * h + 1) * 32 + L];
            mma16816(acc[0][0], (const unsigned*)&A0, W0.x, W0.z);
            mma16816(acc[1][0], (const unsigned*)&A1, W0.x, W0.z);
            mma16816(acc[2][0], (const unsigned*)&A2, W0.x, W0.z);
            mma16816(acc[3][0], (const unsigned*)&A3, W0.x, W0.z);
            mma16816(acc[0][1], (const unsigned*)&A0, W0.y, W0.w);
            mma16816(acc[1][1], (const unsigned*)&A1, W0.y, W0.w);
            mma16816(acc[2][1], (const unsigned*)&A2, W0.y, W0.w);
            mma16816(acc[3][1], (const unsigned*)&A3, W0.y, W0.w);
            mma16816(acc[0][2], (const unsigned*)&A0, W1.x, W1.z);
            mma16816(acc[1][2], (const unsigned*)&A1, W1.x, W1.z);
            mma16816(acc[2][2], (const unsigned*)&A2, W1.x, W1.z);
            mma16816(acc[3][2], (const unsigned*)&A3, W1.x, W1.z);
            mma16816(acc[0][3], (const unsigned*)&A0, W1.y, W1.w);
            mma16816(acc[1][3], (const unsigned*)&A1, W1.y, W1.w);
            mma16816(acc[2][3], (const unsigned*)&A2, W1.y, W1.w);
            mma16816(acc[3][3], (const unsigned*)&A3, W1.y, W1.w);
        }
    }

    // store this warp's GEMM half-tile (non-atomic, private slot)
    float* dst = g_part + ((size_t)bx * 3 + g) * (H * H);
    const int r = L >> 2;
    const int qq = (L & 3) * 2;
#pragma unroll
    for (int m = 0; m < 4; m++)
#pragma unroll
        for (int jl = 0; jl < 4; jl++) {
            const int row0 = m * 16 + r;
            const int col = (4 * h + jl) * 8 + qq;
            *(float2*)(dst + row0 * H + col)       = make_float2(acc[m][jl][0], acc[m][jl][1]);
            *(float2*)(dst + (row0 + 8) * H + col) = make_float2(acc[m][jl][2], acc[m][jl][3]);
        }
}

// grid (16, 24), 256 threads. Sums 55 splits with the channel reversal mapping,
// writes out and a per-block partial total (no atomics, no zeroing).
__global__ void hist_reduce(float* __restrict__ out) {
    const int lc = blockIdx.y;
    const int c = lc % 3, lidx = lc / 3;
    const int e = blockIdx.x * 256 + threadIdx.x;  // 0..4095
    const int u = e >> 6, v = e & 63;
    int se;
    if (c == 0)      se = e;                        // identity
    else if (c == 1) se = ((63 - u) << 6) | v;      // row reversal
    else             se = 4095 - e;                 // row+col reversal
    const float* __restrict__ src =
        g_part + ((size_t)(lidx * NSPLIT) * 3 + c) * (H * H) + se;
    float s = 0.0f;
#pragma unroll 5
    for (int sp = 0; sp < NSPLIT; sp++) s += src[(size_t)sp * 3 * (H * H)];
    out[lc * (H * H) + e] = s;

    __shared__ float red[256];
    red[threadIdx.x] = s;
    __syncthreads();
#pragma unroll
    for (int st = 128; st > 0; st >>= 1) {
        if (threadIdx.x < st) red[threadIdx.x] += red[threadIdx.x + st];
        __syncthreads();
    }
    if (threadIdx.x == 0)
        g_bsum[lc * 16 + blockIdx.x] = red[0];
}

// grid 384, 256 threads. Each block covers 256 contiguous outputs (same l).
__global__ void hist_norm(float* __restrict__ out) {
    __shared__ float red[48];
    const int l = blockIdx.x / 48;                  // 12288 per l / 256 = 48 blocks
    if (threadIdx.x < 48) red[threadIdx.x] = g_bsum[l * 48 + threadIdx.x];
    __syncthreads();
    float tot = 1e-6f;
#pragma unroll
    for (int k = 0; k < 48; k++) tot += red[k];
    const int idx = blockIdx.x * 256 + threadIdx.x;
    out[idx] = out[idx] / tot;
}

extern "C" void kernel_launch(void* const* d_in, const int* in_sizes, int n_in,
                              void* d_out, int out_size) {
    const float* x = (const float*)d_in[0];
    float* out = (float*)d_out;
    (void)in_sizes; (void)n_in; (void)out_size;

    hist_main<<<NCTA, 192>>>(x);
    hist_reduce<<<dim3(16, 24), 256>>>(out);
    hist_norm<<<384, 256>>>(out);
}